// round 15
// baseline (speedup 1.0000x reference)
#include <cuda_runtime.h>
#include <cuda_bf16.h>

#define S_LEN 2048
#define B_DIM 32
#define H_DIM 1024
#define M_TOT (S_LEN * B_DIM)

// ---------------- scratch ----------------
__device__ __nv_bfloat16 g_enc_hi[(size_t)M_TOT * H_DIM];   // 128 MB
__device__ __nv_bfloat16 g_enc_lo[(size_t)M_TOT * H_DIM];   // 128 MB
__device__ __nv_bfloat16 g_w2_hi[H_DIM * H_DIM];
__device__ __nv_bfloat16 g_w2_lo[H_DIM * H_DIM];
__device__ float g_t1[B_DIM * H_DIM];
__device__ float g_scores[B_DIM * S_LEN];
__device__ int g_off[B_DIM + 1];
__device__ int g_total;

// ---------------- helpers ----------------
__device__ __forceinline__ unsigned smem_u32(const void* p) {
    unsigned a;
    asm("{ .reg .u64 t; cvta.to.shared.u64 t, %1; cvt.u32.u64 %0, t; }" : "=r"(a) : "l"(p));
    return a;
}
__device__ __forceinline__ uint4 ldsm_x4(unsigned addr) {
    uint4 r;
    asm volatile("ldmatrix.sync.aligned.m8n8.x4.shared.b16 {%0,%1,%2,%3}, [%4];"
                 : "=r"(r.x), "=r"(r.y), "=r"(r.z), "=r"(r.w) : "r"(addr));
    return r;
}
__device__ __forceinline__ void mma_bf16(float* c, uint4 a, unsigned b0, unsigned b1) {
    asm volatile(
        "mma.sync.aligned.m16n8k16.row.col.f32.bf16.bf16.f32 "
        "{%0,%1,%2,%3}, {%4,%5,%6,%7}, {%8,%9}, {%0,%1,%2,%3};"
        : "+f"(c[0]), "+f"(c[1]), "+f"(c[2]), "+f"(c[3])
        : "r"(a.x), "r"(a.y), "r"(a.z), "r"(a.w), "r"(b0), "r"(b1));
}
__device__ __forceinline__ unsigned pack_bf16x2(float f0, float f1) {
    unsigned r;
    asm("cvt.rn.bf16x2.f32 %0, %1, %2;" : "=r"(r) : "f"(f1), "f"(f0));
    return r;
}
__device__ __forceinline__ void cp_async16(unsigned sdst, const void* gsrc) {
    unsigned long long g;
    asm("cvta.to.global.u64 %0, %1;" : "=l"(g) : "l"(gsrc));
    asm volatile("cp.async.cg.shared.global [%0], [%1], 16;" :: "r"(sdst), "l"(g) : "memory");
}
#define CP_COMMIT() asm volatile("cp.async.commit_group;" ::: "memory")
#define CP_WAIT0()  asm volatile("cp.async.wait_group 0;" ::: "memory")
#define CP_WAIT1()  asm volatile("cp.async.wait_group 1;" ::: "memory")

// compact index -> (batch, s): largest b with soff[b] <= ci
__device__ __forceinline__ int2 rowmap(const int* soff, int ci) {
    int lo = 0, hi = 32;
    while (lo < hi) {
        int mid = (lo + hi + 1) >> 1;
        if (soff[mid] <= ci) lo = mid; else hi = mid - 1;
    }
    return make_int2(lo, ci - soff[lo]);
}

// rational tanh, 4 at a time, one Newton-refined RCP
__device__ __forceinline__ void tanh4(const float* x, float* y) {
    float al[4], be[4];
#pragma unroll
    for (int i = 0; i < 4; i++) {
        float xc = fminf(fmaxf(x[i], -7.90531110763549805f), 7.90531110763549805f);
        float t = xc * xc;
        float a = -2.76076847742355e-16f;
        a = fmaf(a, t, 2.00018790482477e-13f);
        a = fmaf(a, t, -8.60467152213735e-11f);
        a = fmaf(a, t, 5.12229709037114e-08f);
        a = fmaf(a, t, 1.48572235717979e-05f);
        a = fmaf(a, t, 6.37261928875436e-04f);
        a = fmaf(a, t, 4.89352455891786e-03f);
        al[i] = xc * a;
        float b = 1.19825839466702e-06f;
        b = fmaf(b, t, 1.18534705686654e-04f);
        b = fmaf(b, t, 2.26843463243900e-03f);
        be[i] = fmaf(b, t, 4.89352518554385e-03f);
    }
    float p01 = be[0] * be[1];
    float p23 = be[2] * be[3];
    float p = p01 * p23;
    float r;
    asm("rcp.approx.f32 %0, %1;" : "=f"(r) : "f"(p));
    r = r * fmaf(-p, r, 2.0f);
    float q01 = r * p23, q23 = r * p01;
    y[0] = al[0] * (q01 * be[1]);
    y[1] = al[1] * (q01 * be[0]);
    y[2] = al[2] * (q23 * be[3]);
    y[3] = al[3] * (q23 * be[2]);
}

// ---------------- fused prep kernel ----------------
#define PREP_ENC_BLKS   16384
#define PREP_W2_BLKS    1024
#define PREP_T1_BLKS    128
#define PREP_INIT_BLKS  256
#define PREP_GRID (PREP_ENC_BLKS + PREP_W2_BLKS + PREP_T1_BLKS + PREP_INIT_BLKS + 1)

__global__ void k_prep(const float4* __restrict__ enc4,
                       const float* __restrict__ attn_w,
                       const float* __restrict__ attn_b,
                       const float* __restrict__ hidden,
                       const int* __restrict__ lens,
                       float* __restrict__ ctx) {
    int blk = blockIdx.x;
    int tid = threadIdx.x;
    if (blk < PREP_ENC_BLKS) {
        size_t i0 = ((size_t)blk * 256 + tid) * 4;     // float4 index; 256 float4/row
        int row = (int)(i0 >> 8);
        int b = row & (B_DIM - 1), s = row >> 5;
        if (s >= __ldg(&lens[b])) return;
        float4 x[4];
#pragma unroll
        for (int i = 0; i < 4; i++) x[i] = enc4[i0 + i];
        unsigned hi[8], lo[8];
#pragma unroll
        for (int i = 0; i < 4; i++) {
            float hx = __bfloat162float(__float2bfloat16(x[i].x));
            float hy = __bfloat162float(__float2bfloat16(x[i].y));
            float hz = __bfloat162float(__float2bfloat16(x[i].z));
            float hw = __bfloat162float(__float2bfloat16(x[i].w));
            hi[i * 2]     = pack_bf16x2(x[i].x, x[i].y);
            hi[i * 2 + 1] = pack_bf16x2(x[i].z, x[i].w);
            lo[i * 2]     = pack_bf16x2(x[i].x - hx, x[i].y - hy);
            lo[i * 2 + 1] = pack_bf16x2(x[i].z - hz, x[i].w - hw);
        }
        uint4* dh = (uint4*)(g_enc_hi + i0 * 4);
        uint4* dl = (uint4*)(g_enc_lo + i0 * 4);
        dh[0] = make_uint4(hi[0], hi[1], hi[2], hi[3]);
        dh[1] = make_uint4(hi[4], hi[5], hi[6], hi[7]);
        dl[0] = make_uint4(lo[0], lo[1], lo[2], lo[3]);
        dl[1] = make_uint4(lo[4], lo[5], lo[6], lo[7]);
    } else if (blk < PREP_ENC_BLKS + PREP_W2_BLKS) {
        int i = (blk - PREP_ENC_BLKS) * 256 + tid;
        int row = i >> 8, c4 = i & 255;
        float4 x = *(const float4*)(attn_w + (size_t)row * (2 * H_DIM) + H_DIM + c4 * 4);
        float hx = __bfloat162float(__float2bfloat16(x.x));
        float hy = __bfloat162float(__float2bfloat16(x.y));
        float hz = __bfloat162float(__float2bfloat16(x.z));
        float hw = __bfloat162float(__float2bfloat16(x.w));
        ((uint2*)g_w2_hi)[i] = make_uint2(pack_bf16x2(x.x, x.y), pack_bf16x2(x.z, x.w));
        ((uint2*)g_w2_lo)[i] = make_uint2(pack_bf16x2(x.x - hx, x.y - hy),
                                          pack_bf16x2(x.z - hz, x.w - hw));
    } else if (blk < PREP_ENC_BLKS + PREP_W2_BLKS + PREP_T1_BLKS) {
        // one warp per h: W1 row cached in registers, loop over all 32 b
        int h = (blk - PREP_ENC_BLKS - PREP_W2_BLKS) * 8 + (tid >> 5);
        int lane = tid & 31;
        const float4* wp = (const float4*)(attn_w + (size_t)h * 2 * H_DIM);
        float4 wreg[8];
#pragma unroll
        for (int i = 0; i < 8; i++) wreg[i] = wp[i * 32 + lane];
        float bias = attn_b[h];
#pragma unroll 4
        for (int b = 0; b < B_DIM; b++) {
            const float4* hp = (const float4*)(hidden + (size_t)b * H_DIM);
            float acc = 0.f;
#pragma unroll
            for (int i = 0; i < 8; i++) {
                float4 hv = hp[i * 32 + lane];
                acc += hv.x * wreg[i].x + hv.y * wreg[i].y +
                       hv.z * wreg[i].z + hv.w * wreg[i].w;
            }
#pragma unroll
            for (int off = 16; off; off >>= 1)
                acc += __shfl_down_sync(0xffffffffu, acc, off);
            if (lane == 0) g_t1[b * H_DIM + h] = acc + bias;
        }
    } else if (blk < PREP_ENC_BLKS + PREP_W2_BLKS + PREP_T1_BLKS + PREP_INIT_BLKS) {
        int i = (blk - PREP_ENC_BLKS - PREP_W2_BLKS - PREP_T1_BLKS) * 256 + tid;
        if (i < B_DIM * S_LEN) g_scores[i] = 0.f;
        if (i < B_DIM * H_DIM) ctx[i] = 0.f;
    } else {
        if (tid == 0) {
            int acc = 0;
            g_off[0] = 0;
            for (int b = 0; b < B_DIM; b++) { acc += lens[b]; g_off[b + 1] = acc; }
            g_total = acc;
        }
    }
}

// ---------------- K1: compacted-row GEMM, 128x128 CTA, 2 CTAs/SM ----------------
#define BM 128
#define BN 128
#define BK 32
#define A_HI 0
#define A_LO 8192
#define B_HI 16384
#define B_LO 24576
#define STAGE_B 32768
#define NSTAGE 3
#define VS_OFF  (NSTAGE * STAGE_B)          // 98304: 128 f32
#define SROW_OFF (VS_OFF + 512)             // 98816: 128 f32
#define SOFF_OFF (SROW_OFF + 512)           // 99328: 33 ints
#define K1_SMEM  (SOFF_OFF + 144)           // 99472

__device__ __forceinline__ unsigned sw_off(int row, int c16) {
    return (unsigned)row * 64u + (unsigned)((c16 ^ ((row >> 1) & 3)) << 4);
}

__device__ __forceinline__ void fill_stage(unsigned sb, const size_t* gA, int n0,
                                           int kk, int tid) {
    const int c16 = tid & 3;
    const int lr = tid >> 2;
#pragma unroll
    for (int i = 0; i < 4; i++) {
        size_t goff = gA[i] + kk + c16 * 8;
        unsigned soff = sw_off(i * 32 + lr, c16);
        cp_async16(sb + A_HI + soff, g_enc_hi + goff);
        cp_async16(sb + A_LO + soff, g_enc_lo + goff);
    }
#pragma unroll
    for (int i = 0; i < 4; i++) {
        int idx = i * 128 + tid;
        int row = idx >> 2;
        size_t goff = (size_t)(n0 + row) * H_DIM + kk + c16 * 8;
        unsigned soff = sw_off(row, c16);
        cp_async16(sb + B_HI + soff, g_w2_hi + goff);
        cp_async16(sb + B_LO + soff, g_w2_lo + goff);
    }
}

__global__ void __launch_bounds__(128, 2) k1_gemm(const float* __restrict__ v) {
    const int total = g_total;
    const int m0c = blockIdx.y * BM;
    if (m0c >= total) return;

    extern __shared__ char smem[];
    const unsigned sbase = smem_u32(smem);
    const int tid = threadIdx.x;
    const int wid = tid >> 5;
    const int L = tid & 31;
    const int wm = wid & 1;
    const int wn = wid >> 1;
    const int n0 = blockIdx.x * BN;

    float* vs = (float*)(smem + VS_OFF);
    float* srow = (float*)(smem + SROW_OFF);
    int* soff = (int*)(smem + SOFF_OFF);
    vs[tid] = v[n0 + tid];
    srow[tid] = 0.f;
    if (tid < 33) soff[tid] = g_off[tid];
    __syncthreads();

    size_t gA[4];
#pragma unroll
    for (int i = 0; i < 4; i++) {
        int ci = m0c + i * 32 + (tid >> 2);
        ci = min(ci, total - 1);
        int2 bs = rowmap(soff, ci);
        gA[i] = (size_t)(bs.y * B_DIM + bs.x) * H_DIM;   // r = s*B + b
    }

    fill_stage(sbase, gA, n0, 0, tid);
    CP_COMMIT();
    fill_stage(sbase + STAGE_B, gA, n0, BK, tid);
    CP_COMMIT();

    float acc[4][8][4];
#pragma unroll
    for (int i = 0; i < 4; i++)
#pragma unroll
        for (int j = 0; j < 8; j++)
#pragma unroll
            for (int e = 0; e < 4; e++) acc[i][j][e] = 0.f;

    const int a_r = wm * 64 + ((L >> 3) & 1) * 8 + (L & 7);
    const int a_c = (L >> 4);
    const int b_r = wn * 64 + (L >> 4) * 8 + (L & 7);
    const int b_c = ((L >> 3) & 1);

    const int NKT = H_DIM / BK;              // 32
    int slot = 0, nslot = 2;
    for (int kt = 0; kt < NKT; kt++) {
        if (kt + 1 < NKT) { CP_WAIT1(); } else { CP_WAIT0(); }
        __syncthreads();
        if (kt + 2 < NKT) {
            fill_stage(sbase + nslot * STAGE_B, gA, n0, (kt + 2) * BK, tid);
            CP_COMMIT();
        }
        const unsigned sb = sbase + slot * STAGE_B;
#pragma unroll
        for (int ks = 0; ks < 2; ks++) {
            uint4 ah[4], al[4], bh[4], bl[4];
#pragma unroll
            for (int mf = 0; mf < 4; mf++) {
                int row = a_r + mf * 16;
                unsigned off = sw_off(row, ks * 2 + a_c);
                ah[mf] = ldsm_x4(sb + A_HI + off);
                al[mf] = ldsm_x4(sb + A_LO + off);
            }
#pragma unroll
            for (int nf2 = 0; nf2 < 4; nf2++) {
                int row = b_r + nf2 * 16;
                unsigned off = sw_off(row, ks * 2 + b_c);
                bh[nf2] = ldsm_x4(sb + B_HI + off);
                bl[nf2] = ldsm_x4(sb + B_LO + off);
            }
#pragma unroll
            for (int mf = 0; mf < 4; mf++)
#pragma unroll
                for (int nf2 = 0; nf2 < 4; nf2++) {
                    mma_bf16(acc[mf][nf2 * 2],     ah[mf], bh[nf2].x, bh[nf2].y);
                    mma_bf16(acc[mf][nf2 * 2 + 1], ah[mf], bh[nf2].z, bh[nf2].w);
                }
#pragma unroll
            for (int mf = 0; mf < 4; mf++)
#pragma unroll
                for (int nf2 = 0; nf2 < 4; nf2++) {
                    mma_bf16(acc[mf][nf2 * 2],     ah[mf], bl[nf2].x, bl[nf2].y);
                    mma_bf16(acc[mf][nf2 * 2 + 1], ah[mf], bl[nf2].z, bl[nf2].w);
                }
#pragma unroll
            for (int mf = 0; mf < 4; mf++)
#pragma unroll
                for (int nf2 = 0; nf2 < 4; nf2++) {
                    mma_bf16(acc[mf][nf2 * 2],     al[mf], bh[nf2].x, bh[nf2].y);
                    mma_bf16(acc[mf][nf2 * 2 + 1], al[mf], bh[nf2].z, bh[nf2].w);
                }
        }
        slot = (slot == 2) ? 0 : slot + 1;
        nslot = (nslot == 2) ? 0 : nslot + 1;
    }

    // ---------------- epilogue ----------------
    const int q = L >> 2;
#pragma unroll
    for (int mf = 0; mf < 4; mf++) {
        const int rc0 = m0c + wm * 64 + mf * 16 + q;
        const int rc1 = rc0 + 8;
        int2 bs0 = rowmap(soff, min(rc0, total - 1));
        int2 bs1 = rowmap(soff, min(rc1, total - 1));
        float2 t0a[8], t1a[8];
#pragma unroll
        for (int nf = 0; nf < 8; nf++) {
            const int c = n0 + wn * 64 + nf * 8 + (L & 3) * 2;
            t0a[nf] = __ldg((const float2*)(g_t1 + (size_t)bs0.x * H_DIM + c));
            t1a[nf] = __ldg((const float2*)(g_t1 + (size_t)bs1.x * H_DIM + c));
        }
        float rp0 = 0.f, rp1 = 0.f;
#pragma unroll
        for (int nf = 0; nf < 8; nf++) {
            const int cl = wn * 64 + nf * 8 + (L & 3) * 2;
            float x[4], y[4];
            x[0] = acc[mf][nf][0] + t0a[nf].x;
            x[1] = acc[mf][nf][1] + t0a[nf].y;
            x[2] = acc[mf][nf][2] + t1a[nf].x;
            x[3] = acc[mf][nf][3] + t1a[nf].y;
            tanh4(x, y);
            rp0 += y[0] * vs[cl] + y[1] * vs[cl + 1];
            rp1 += y[2] * vs[cl] + y[3] * vs[cl + 1];
        }
        rp0 += __shfl_xor_sync(0xffffffffu, rp0, 1);
        rp0 += __shfl_xor_sync(0xffffffffu, rp0, 2);
        rp1 += __shfl_xor_sync(0xffffffffu, rp1, 1);
        rp1 += __shfl_xor_sync(0xffffffffu, rp1, 2);
        if ((L & 3) == 0) {
            atomicAdd(&srow[wm * 64 + mf * 16 + q], rp0);
            atomicAdd(&srow[wm * 64 + mf * 16 + q + 8], rp1);
        }
    }
    __syncthreads();
    {
        int rc = m0c + tid;
        if (rc < total) {
            int2 bs = rowmap(soff, rc);
            atomicAdd(&g_scores[bs.x * S_LEN + bs.y], srow[tid]);
        }
    }
}

// ---------------- softmax (512 threads) ----------------
__global__ void k2_softmax(const int* __restrict__ lens, float* __restrict__ wout) {
    __shared__ float red[512];
    int b = blockIdx.x;
    int len = lens[b];
    const float* sc = g_scores + (size_t)b * S_LEN;
    int tid = threadIdx.x;

    float mx = -3.4e38f;
    for (int s = tid; s < len; s += 512) mx = fmaxf(mx, sc[s]);
    red[tid] = mx;
    __syncthreads();
    for (int off = 256; off; off >>= 1) {
        if (tid < off) red[tid] = fmaxf(red[tid], red[tid + off]);
        __syncthreads();
    }
    mx = red[0];
    __syncthreads();

    float sum = 0.f;
    for (int s = tid; s < len; s += 512) sum += expf(sc[s] - mx);
    red[tid] = sum;
    __syncthreads();
    for (int off = 256; off; off >>= 1) {
        if (tid < off) red[tid] += red[tid + off];
        __syncthreads();
    }
    float inv = 1.f / red[0];

    for (int s = tid; s < S_LEN; s += 512)
        wout[(size_t)b * S_LEN + s] = (s < len) ? expf(sc[s] - mx) * inv : 0.f;
}

// ---------------- context ----------------
#define NCHUNK 64
__global__ void k3_context(const float* __restrict__ enc,
                           const float* __restrict__ wts,
                           const int* __restrict__ lens,
                           float* __restrict__ ctx) {
    int b = blockIdx.y;
    int len = lens[b];
    int s0 = blockIdx.x * (S_LEN / NCHUNK);
    int s1 = min(s0 + (S_LEN / NCHUNK), len);
    if (s0 >= s1) return;
    int h = threadIdx.x * 4;
    float4 acc = make_float4(0.f, 0.f, 0.f, 0.f);
    for (int s = s0; s < s1; s++) {
        float w = __ldg(&wts[(size_t)b * S_LEN + s]);
        float4 e = *(const float4*)(enc + ((size_t)(s * B_DIM + b)) * H_DIM + h);
        acc.x += w * e.x; acc.y += w * e.y; acc.z += w * e.z; acc.w += w * e.w;
    }
    float* c = ctx + (size_t)b * H_DIM + h;
    atomicAdd(c + 0, acc.x);
    atomicAdd(c + 1, acc.y);
    atomicAdd(c + 2, acc.z);
    atomicAdd(c + 3, acc.w);
}

// ---------------- launcher ----------------
extern "C" void kernel_launch(void* const* d_in, const int* in_sizes, int n_in,
                              void* d_out, int out_size) {
    const float* hidden = (const float*)d_in[0];
    const float* enc    = (const float*)d_in[1];
    const int*   lens   = (const int*)d_in[2];
    const float* attn_w = (const float*)d_in[3];
    const float* attn_b = (const float*)d_in[4];
    const float* v      = (const float*)d_in[5];

    float* out = (float*)d_out;
    float* ctx = out;
    float* wts = out + B_DIM * H_DIM;

    cudaFuncSetAttribute(k1_gemm, cudaFuncAttributeMaxDynamicSharedMemorySize, K1_SMEM);

    k_prep<<<PREP_GRID, 256>>>((const float4*)enc, attn_w, attn_b, hidden, lens, ctx);
    dim3 g1(H_DIM / BN, M_TOT / BM);     // (8, 512); CTAs beyond g_total exit early
    k1_gemm<<<g1, 128, K1_SMEM>>>(v);
    k2_softmax<<<B_DIM, 512>>>(lens, wts);
    dim3 g3(NCHUNK, B_DIM);
    k3_context<<<g3, 256>>>(enc, wts, lens, ctx);
}

// round 16
// speedup vs baseline: 1.0314x; 1.0314x over previous
#include <cuda_runtime.h>
#include <cuda_bf16.h>

#define S_LEN 2048
#define B_DIM 32
#define H_DIM 1024
#define M_TOT (S_LEN * B_DIM)

// ---------------- scratch ----------------
__device__ __nv_bfloat16 g_enc_hi[(size_t)M_TOT * H_DIM];   // 128 MB
__device__ __nv_bfloat16 g_enc_lo[(size_t)M_TOT * H_DIM];   // 128 MB
__device__ __nv_bfloat16 g_w2_hi[H_DIM * H_DIM];
__device__ __nv_bfloat16 g_w2_lo[H_DIM * H_DIM];
__device__ float g_t1[B_DIM * H_DIM];
__device__ float g_scores[B_DIM * S_LEN];
__device__ int g_off[B_DIM + 1];
__device__ int g_total;

// ---------------- helpers ----------------
__device__ __forceinline__ unsigned smem_u32(const void* p) {
    unsigned a;
    asm("{ .reg .u64 t; cvta.to.shared.u64 t, %1; cvt.u32.u64 %0, t; }" : "=r"(a) : "l"(p));
    return a;
}
__device__ __forceinline__ uint4 ldsm_x4(unsigned addr) {
    uint4 r;
    asm volatile("ldmatrix.sync.aligned.m8n8.x4.shared.b16 {%0,%1,%2,%3}, [%4];"
                 : "=r"(r.x), "=r"(r.y), "=r"(r.z), "=r"(r.w) : "r"(addr));
    return r;
}
__device__ __forceinline__ void mma_bf16(float* c, uint4 a, unsigned b0, unsigned b1) {
    asm volatile(
        "mma.sync.aligned.m16n8k16.row.col.f32.bf16.bf16.f32 "
        "{%0,%1,%2,%3}, {%4,%5,%6,%7}, {%8,%9}, {%0,%1,%2,%3};"
        : "+f"(c[0]), "+f"(c[1]), "+f"(c[2]), "+f"(c[3])
        : "r"(a.x), "r"(a.y), "r"(a.z), "r"(a.w), "r"(b0), "r"(b1));
}
__device__ __forceinline__ unsigned pack_bf16x2(float f0, float f1) {
    unsigned r;
    asm("cvt.rn.bf16x2.f32 %0, %1, %2;" : "=r"(r) : "f"(f1), "f"(f0));
    return r;
}
__device__ __forceinline__ void cp_async16(unsigned sdst, const void* gsrc) {
    unsigned long long g;
    asm("cvta.to.global.u64 %0, %1;" : "=l"(g) : "l"(gsrc));
    asm volatile("cp.async.cg.shared.global [%0], [%1], 16;" :: "r"(sdst), "l"(g) : "memory");
}
#define CP_COMMIT() asm volatile("cp.async.commit_group;" ::: "memory")
#define CP_WAIT0()  asm volatile("cp.async.wait_group 0;" ::: "memory")
#define CP_WAIT1()  asm volatile("cp.async.wait_group 1;" ::: "memory")

// compact index -> (batch, s): largest b with soff[b] <= ci
__device__ __forceinline__ int2 rowmap(const int* soff, int ci) {
    int lo = 0, hi = 32;
    while (lo < hi) {
        int mid = (lo + hi + 1) >> 1;
        if (soff[mid] <= ci) lo = mid; else hi = mid - 1;
    }
    return make_int2(lo, ci - soff[lo]);
}

// rational tanh, 4 at a time, one Newton-refined RCP
__device__ __forceinline__ void tanh4(const float* x, float* y) {
    float al[4], be[4];
#pragma unroll
    for (int i = 0; i < 4; i++) {
        float xc = fminf(fmaxf(x[i], -7.90531110763549805f), 7.90531110763549805f);
        float t = xc * xc;
        float a = -2.76076847742355e-16f;
        a = fmaf(a, t, 2.00018790482477e-13f);
        a = fmaf(a, t, -8.60467152213735e-11f);
        a = fmaf(a, t, 5.12229709037114e-08f);
        a = fmaf(a, t, 1.48572235717979e-05f);
        a = fmaf(a, t, 6.37261928875436e-04f);
        a = fmaf(a, t, 4.89352455891786e-03f);
        al[i] = xc * a;
        float b = 1.19825839466702e-06f;
        b = fmaf(b, t, 1.18534705686654e-04f);
        b = fmaf(b, t, 2.26843463243900e-03f);
        be[i] = fmaf(b, t, 4.89352518554385e-03f);
    }
    float p01 = be[0] * be[1];
    float p23 = be[2] * be[3];
    float p = p01 * p23;
    float r;
    asm("rcp.approx.f32 %0, %1;" : "=f"(r) : "f"(p));
    r = r * fmaf(-p, r, 2.0f);
    float q01 = r * p23, q23 = r * p01;
    y[0] = al[0] * (q01 * be[1]);
    y[1] = al[1] * (q01 * be[0]);
    y[2] = al[2] * (q23 * be[3]);
    y[3] = al[3] * (q23 * be[2]);
}

// ---------------- fused prep kernel (enc split w/ len skip + w2 + t1 + init + prefix) ----------------
#define PREP_ENC_BLKS   16384
#define PREP_W2_BLKS    1024
#define PREP_T1_BLKS    4096
#define PREP_INIT_BLKS  256
#define PREP_GRID (PREP_ENC_BLKS + PREP_W2_BLKS + PREP_T1_BLKS + PREP_INIT_BLKS + 1)

__global__ void k_prep(const float4* __restrict__ enc4,
                       const float* __restrict__ attn_w,
                       const float* __restrict__ attn_b,
                       const float* __restrict__ hidden,
                       const int* __restrict__ lens,
                       float* __restrict__ ctx) {
    int blk = blockIdx.x;
    int tid = threadIdx.x;
    if (blk < PREP_ENC_BLKS) {
        size_t i0 = ((size_t)blk * 256 + tid) * 4;     // float4 index; 256 float4/row
        int row = (int)(i0 >> 8);
        int b = row & (B_DIM - 1), s = row >> 5;
        if (s >= __ldg(&lens[b])) return;
        float4 x[4];
#pragma unroll
        for (int i = 0; i < 4; i++) x[i] = enc4[i0 + i];
        unsigned hi[8], lo[8];
#pragma unroll
        for (int i = 0; i < 4; i++) {
            float hx = __bfloat162float(__float2bfloat16(x[i].x));
            float hy = __bfloat162float(__float2bfloat16(x[i].y));
            float hz = __bfloat162float(__float2bfloat16(x[i].z));
            float hw = __bfloat162float(__float2bfloat16(x[i].w));
            hi[i * 2]     = pack_bf16x2(x[i].x, x[i].y);
            hi[i * 2 + 1] = pack_bf16x2(x[i].z, x[i].w);
            lo[i * 2]     = pack_bf16x2(x[i].x - hx, x[i].y - hy);
            lo[i * 2 + 1] = pack_bf16x2(x[i].z - hz, x[i].w - hw);
        }
        uint4* dh = (uint4*)(g_enc_hi + i0 * 4);
        uint4* dl = (uint4*)(g_enc_lo + i0 * 4);
        dh[0] = make_uint4(hi[0], hi[1], hi[2], hi[3]);
        dh[1] = make_uint4(hi[4], hi[5], hi[6], hi[7]);
        dl[0] = make_uint4(lo[0], lo[1], lo[2], lo[3]);
        dl[1] = make_uint4(lo[4], lo[5], lo[6], lo[7]);
    } else if (blk < PREP_ENC_BLKS + PREP_W2_BLKS) {
        int i = (blk - PREP_ENC_BLKS) * 256 + tid;
        int row = i >> 8, c4 = i & 255;
        float4 x = *(const float4*)(attn_w + (size_t)row * (2 * H_DIM) + H_DIM + c4 * 4);
        float hx = __bfloat162float(__float2bfloat16(x.x));
        float hy = __bfloat162float(__float2bfloat16(x.y));
        float hz = __bfloat162float(__float2bfloat16(x.z));
        float hw = __bfloat162float(__float2bfloat16(x.w));
        ((uint2*)g_w2_hi)[i] = make_uint2(pack_bf16x2(x.x, x.y), pack_bf16x2(x.z, x.w));
        ((uint2*)g_w2_lo)[i] = make_uint2(pack_bf16x2(x.x - hx, x.y - hy),
                                          pack_bf16x2(x.z - hz, x.w - hw));
    } else if (blk < PREP_ENC_BLKS + PREP_W2_BLKS + PREP_T1_BLKS) {
        int w = (blk - PREP_ENC_BLKS - PREP_W2_BLKS) * 8 + (tid >> 5);
        int lane = tid & 31;
        int b = w >> 10;
        int h = w & (H_DIM - 1);
        const float4* hp = (const float4*)(hidden + (size_t)b * H_DIM);
        const float4* wp = (const float4*)(attn_w + (size_t)h * 2 * H_DIM);
        float acc = 0.f;
#pragma unroll
        for (int i = 0; i < 8; i++) {
            int idx = i * 32 + lane;
            float4 hv = hp[idx];
            float4 wv = wp[idx];
            acc += hv.x * wv.x + hv.y * wv.y + hv.z * wv.z + hv.w * wv.w;
        }
#pragma unroll
        for (int off = 16; off; off >>= 1) acc += __shfl_down_sync(0xffffffffu, acc, off);
        if (lane == 0) g_t1[w] = acc + attn_b[h];
    } else if (blk < PREP_ENC_BLKS + PREP_W2_BLKS + PREP_T1_BLKS + PREP_INIT_BLKS) {
        int i = (blk - PREP_ENC_BLKS - PREP_W2_BLKS - PREP_T1_BLKS) * 256 + tid;
        if (i < B_DIM * S_LEN) g_scores[i] = 0.f;
        if (i < B_DIM * H_DIM) ctx[i] = 0.f;
    } else {
        if (tid == 0) {
            int acc = 0;
            g_off[0] = 0;
            for (int b = 0; b < B_DIM; b++) { acc += lens[b]; g_off[b + 1] = acc; }
            g_total = acc;
        }
    }
}

// ---------------- K1: compacted-row GEMM, 128x128 CTA, 2 CTAs/SM ----------------
#define BM 128
#define BN 128
#define BK 32
#define A_HI 0
#define A_LO 8192
#define B_HI 16384
#define B_LO 24576
#define STAGE_B 32768
#define NSTAGE 3
#define VS_OFF  (NSTAGE * STAGE_B)          // 98304: 128 f32
#define SROW_OFF (VS_OFF + 512)             // 98816: 128 f32
#define SOFF_OFF (SROW_OFF + 512)           // 99328: 33 ints
#define K1_SMEM  (SOFF_OFF + 144)           // 99472

__device__ __forceinline__ unsigned sw_off(int row, int c16) {
    return (unsigned)row * 64u + (unsigned)((c16 ^ ((row >> 1) & 3)) << 4);
}

__device__ __forceinline__ void fill_stage(unsigned sb, const size_t* gA, int n0,
                                           int kk, int tid) {
    const int c16 = tid & 3;
    const int lr = tid >> 2;
#pragma unroll
    for (int i = 0; i < 4; i++) {
        size_t goff = gA[i] + kk + c16 * 8;
        unsigned soff = sw_off(i * 32 + lr, c16);
        cp_async16(sb + A_HI + soff, g_enc_hi + goff);
        cp_async16(sb + A_LO + soff, g_enc_lo + goff);
    }
#pragma unroll
    for (int i = 0; i < 4; i++) {
        int idx = i * 128 + tid;
        int row = idx >> 2;
        size_t goff = (size_t)(n0 + row) * H_DIM + kk + c16 * 8;
        unsigned soff = sw_off(row, c16);
        cp_async16(sb + B_HI + soff, g_w2_hi + goff);
        cp_async16(sb + B_LO + soff, g_w2_lo + goff);
    }
}

__global__ void __launch_bounds__(128, 2) k1_gemm(const float* __restrict__ v) {
    const int total = g_total;
    const int m0c = blockIdx.y * BM;
    if (m0c >= total) return;

    extern __shared__ char smem[];
    const unsigned sbase = smem_u32(smem);
    const int tid = threadIdx.x;
    const int wid = tid >> 5;
    const int L = tid & 31;
    const int wm = wid & 1;
    const int wn = wid >> 1;
    const int n0 = blockIdx.x * BN;

    float* vs = (float*)(smem + VS_OFF);
    float* srow = (float*)(smem + SROW_OFF);
    int* soff = (int*)(smem + SOFF_OFF);
    vs[tid] = v[n0 + tid];
    srow[tid] = 0.f;
    if (tid < 33) soff[tid] = g_off[tid];
    __syncthreads();

    size_t gA[4];
#pragma unroll
    for (int i = 0; i < 4; i++) {
        int ci = m0c + i * 32 + (tid >> 2);
        ci = min(ci, total - 1);
        int2 bs = rowmap(soff, ci);
        gA[i] = (size_t)(bs.y * B_DIM + bs.x) * H_DIM;   // r = s*B + b
    }

    fill_stage(sbase, gA, n0, 0, tid);
    CP_COMMIT();
    fill_stage(sbase + STAGE_B, gA, n0, BK, tid);
    CP_COMMIT();

    float acc[4][8][4];
#pragma unroll
    for (int i = 0; i < 4; i++)
#pragma unroll
        for (int j = 0; j < 8; j++)
#pragma unroll
            for (int e = 0; e < 4; e++) acc[i][j][e] = 0.f;

    const int a_r = wm * 64 + ((L >> 3) & 1) * 8 + (L & 7);
    const int a_c = (L >> 4);
    const int b_r = wn * 64 + (L >> 4) * 8 + (L & 7);
    const int b_c = ((L >> 3) & 1);

    const int NKT = H_DIM / BK;              // 32
    int slot = 0, nslot = 2;
    for (int kt = 0; kt < NKT; kt++) {
        if (kt + 1 < NKT) { CP_WAIT1(); } else { CP_WAIT0(); }
        __syncthreads();
        if (kt + 2 < NKT) {
            fill_stage(sbase + nslot * STAGE_B, gA, n0, (kt + 2) * BK, tid);
            CP_COMMIT();
        }
        const unsigned sb = sbase + slot * STAGE_B;
#pragma unroll
        for (int ks = 0; ks < 2; ks++) {
            uint4 ah[4], al[4], bh[4], bl[4];
#pragma unroll
            for (int mf = 0; mf < 4; mf++) {
                int row = a_r + mf * 16;
                unsigned off = sw_off(row, ks * 2 + a_c);
                ah[mf] = ldsm_x4(sb + A_HI + off);
                al[mf] = ldsm_x4(sb + A_LO + off);
            }
#pragma unroll
            for (int nf2 = 0; nf2 < 4; nf2++) {
                int row = b_r + nf2 * 16;
                unsigned off = sw_off(row, ks * 2 + b_c);
                bh[nf2] = ldsm_x4(sb + B_HI + off);
                bl[nf2] = ldsm_x4(sb + B_LO + off);
            }
#pragma unroll
            for (int mf = 0; mf < 4; mf++)
#pragma unroll
                for (int nf2 = 0; nf2 < 4; nf2++) {
                    mma_bf16(acc[mf][nf2 * 2],     ah[mf], bh[nf2].x, bh[nf2].y);
                    mma_bf16(acc[mf][nf2 * 2 + 1], ah[mf], bh[nf2].z, bh[nf2].w);
                }
#pragma unroll
            for (int mf = 0; mf < 4; mf++)
#pragma unroll
                for (int nf2 = 0; nf2 < 4; nf2++) {
                    mma_bf16(acc[mf][nf2 * 2],     ah[mf], bl[nf2].x, bl[nf2].y);
                    mma_bf16(acc[mf][nf2 * 2 + 1], ah[mf], bl[nf2].z, bl[nf2].w);
                }
#pragma unroll
            for (int mf = 0; mf < 4; mf++)
#pragma unroll
                for (int nf2 = 0; nf2 < 4; nf2++) {
                    mma_bf16(acc[mf][nf2 * 2],     al[mf], bh[nf2].x, bh[nf2].y);
                    mma_bf16(acc[mf][nf2 * 2 + 1], al[mf], bh[nf2].z, bh[nf2].w);
                }
        }
        slot = (slot == 2) ? 0 : slot + 1;
        nslot = (nslot == 2) ? 0 : nslot + 1;
    }

    // ---------------- epilogue ----------------
    const int q = L >> 2;
#pragma unroll
    for (int mf = 0; mf < 4; mf++) {
        const int rc0 = m0c + wm * 64 + mf * 16 + q;
        const int rc1 = rc0 + 8;
        int2 bs0 = rowmap(soff, min(rc0, total - 1));
        int2 bs1 = rowmap(soff, min(rc1, total - 1));
        float2 t0a[8], t1a[8];
#pragma unroll
        for (int nf = 0; nf < 8; nf++) {
            const int c = n0 + wn * 64 + nf * 8 + (L & 3) * 2;
            t0a[nf] = __ldg((const float2*)(g_t1 + (size_t)bs0.x * H_DIM + c));
            t1a[nf] = __ldg((const float2*)(g_t1 + (size_t)bs1.x * H_DIM + c));
        }
        float rp0 = 0.f, rp1 = 0.f;
#pragma unroll
        for (int nf = 0; nf < 8; nf++) {
            const int cl = wn * 64 + nf * 8 + (L & 3) * 2;
            float x[4], y[4];
            x[0] = acc[mf][nf][0] + t0a[nf].x;
            x[1] = acc[mf][nf][1] + t0a[nf].y;
            x[2] = acc[mf][nf][2] + t1a[nf].x;
            x[3] = acc[mf][nf][3] + t1a[nf].y;
            tanh4(x, y);
            rp0 += y[0] * vs[cl] + y[1] * vs[cl + 1];
            rp1 += y[2] * vs[cl] + y[3] * vs[cl + 1];
        }
        rp0 += __shfl_xor_sync(0xffffffffu, rp0, 1);
        rp0 += __shfl_xor_sync(0xffffffffu, rp0, 2);
        rp1 += __shfl_xor_sync(0xffffffffu, rp1, 1);
        rp1 += __shfl_xor_sync(0xffffffffu, rp1, 2);
        if ((L & 3) == 0) {
            atomicAdd(&srow[wm * 64 + mf * 16 + q], rp0);
            atomicAdd(&srow[wm * 64 + mf * 16 + q + 8], rp1);
        }
    }
    __syncthreads();
    {
        int rc = m0c + tid;
        if (rc < total) {
            int2 bs = rowmap(soff, rc);
            atomicAdd(&g_scores[bs.x * S_LEN + bs.y], srow[tid]);
        }
    }
}

// ---------------- softmax ----------------
__global__ void k2_softmax(const int* __restrict__ lens, float* __restrict__ wout) {
    __shared__ float red[256];
    int b = blockIdx.x;
    int len = lens[b];
    const float* sc = g_scores + (size_t)b * S_LEN;
    int tid = threadIdx.x;

    float mx = -3.4e38f;
    for (int s = tid; s < len; s += 256) mx = fmaxf(mx, sc[s]);
    red[tid] = mx;
    __syncthreads();
    for (int off = 128; off; off >>= 1) {
        if (tid < off) red[tid] = fmaxf(red[tid], red[tid + off]);
        __syncthreads();
    }
    mx = red[0];
    __syncthreads();

    float sum = 0.f;
    for (int s = tid; s < len; s += 256) sum += expf(sc[s] - mx);
    red[tid] = sum;
    __syncthreads();
    for (int off = 128; off; off >>= 1) {
        if (tid < off) red[tid] += red[tid + off];
        __syncthreads();
    }
    float inv = 1.f / red[0];

    for (int s = tid; s < S_LEN; s += 256)
        wout[(size_t)b * S_LEN + s] = (s < len) ? expf(sc[s] - mx) * inv : 0.f;
}

// ---------------- context: s-loop unrolled x4, float4 weight loads ----------------
#define NCHUNK 64
__global__ void k3_context(const float* __restrict__ enc,
                           const float* __restrict__ wts,
                           const int* __restrict__ lens,
                           float* __restrict__ ctx) {
    int b = blockIdx.y;
    int len = lens[b];
    int s0 = blockIdx.x * (S_LEN / NCHUNK);
    int s1 = min(s0 + (S_LEN / NCHUNK), len);
    if (s0 >= s1) return;
    int h = threadIdx.x * 4;
    float4 a0 = make_float4(0.f, 0.f, 0.f, 0.f);
    float4 a1 = make_float4(0.f, 0.f, 0.f, 0.f);
    int s = s0;
    for (; s + 3 < s1; s += 4) {
        float4 w4 = __ldg((const float4*)(wts + (size_t)b * S_LEN + s));   // s0%32==0 -> aligned
        float4 e0 = *(const float4*)(enc + ((size_t)((s + 0) * B_DIM + b)) * H_DIM + h);
        float4 e1 = *(const float4*)(enc + ((size_t)((s + 1) * B_DIM + b)) * H_DIM + h);
        float4 e2 = *(const float4*)(enc + ((size_t)((s + 2) * B_DIM + b)) * H_DIM + h);
        float4 e3 = *(const float4*)(enc + ((size_t)((s + 3) * B_DIM + b)) * H_DIM + h);
        a0.x += w4.x * e0.x; a0.y += w4.x * e0.y; a0.z += w4.x * e0.z; a0.w += w4.x * e0.w;
        a1.x += w4.y * e1.x; a1.y += w4.y * e1.y; a1.z += w4.y * e1.z; a1.w += w4.y * e1.w;
        a0.x += w4.z * e2.x; a0.y += w4.z * e2.y; a0.z += w4.z * e2.z; a0.w += w4.z * e2.w;
        a1.x += w4.w * e3.x; a1.y += w4.w * e3.y; a1.z += w4.w * e3.z; a1.w += w4.w * e3.w;
    }
    for (; s < s1; s++) {
        float w = __ldg(&wts[(size_t)b * S_LEN + s]);
        float4 e = *(const float4*)(enc + ((size_t)(s * B_DIM + b)) * H_DIM + h);
        a0.x += w * e.x; a0.y += w * e.y; a0.z += w * e.z; a0.w += w * e.w;
    }
    float* c = ctx + (size_t)b * H_DIM + h;
    atomicAdd(c + 0, a0.x + a1.x);
    atomicAdd(c + 1, a0.y + a1.y);
    atomicAdd(c + 2, a0.z + a1.z);
    atomicAdd(c + 3, a0.w + a1.w);
}

// ---------------- launcher ----------------
extern "C" void kernel_launch(void* const* d_in, const int* in_sizes, int n_in,
                              void* d_out, int out_size) {
    const float* hidden = (const float*)d_in[0];
    const float* enc    = (const float*)d_in[1];
    const int*   lens   = (const int*)d_in[2];
    const float* attn_w = (const float*)d_in[3];
    const float* attn_b = (const float*)d_in[4];
    const float* v      = (const float*)d_in[5];

    float* out = (float*)d_out;
    float* ctx = out;
    float* wts = out + B_DIM * H_DIM;

    cudaFuncSetAttribute(k1_gemm, cudaFuncAttributeMaxDynamicSharedMemorySize, K1_SMEM);

    k_prep<<<PREP_GRID, 256>>>((const float4*)enc, attn_w, attn_b, hidden, lens, ctx);
    dim3 g1(H_DIM / BN, M_TOT / BM);     // (8, 512); CTAs beyond g_total exit early
    k1_gemm<<<g1, 128, K1_SMEM>>>(v);
    k2_softmax<<<B_DIM, 256>>>(lens, wts);
    dim3 g3(NCHUNK, B_DIM);
    k3_context<<<g3, 256>>>(enc, wts, lens, ctx);
}

// round 17
// speedup vs baseline: 1.0416x; 1.0099x over previous
#include <cuda_runtime.h>
#include <cuda_bf16.h>

#define S_LEN 2048
#define B_DIM 32
#define H_DIM 1024
#define M_TOT (S_LEN * B_DIM)

// ---------------- scratch ----------------
__device__ __nv_bfloat16 g_enc_hi[(size_t)M_TOT * H_DIM];   // 128 MB
__device__ __nv_bfloat16 g_enc_lo[(size_t)M_TOT * H_DIM];   // 128 MB
__device__ __nv_bfloat16 g_w2_hi[H_DIM * H_DIM];
__device__ __nv_bfloat16 g_w2_lo[H_DIM * H_DIM];
__device__ float g_t1[B_DIM * H_DIM];
__device__ float g_scores[B_DIM * S_LEN];
__device__ int g_off[B_DIM + 1];
__device__ int g_total;

// ---------------- helpers ----------------
__device__ __forceinline__ unsigned smem_u32(const void* p) {
    unsigned a;
    asm("{ .reg .u64 t; cvta.to.shared.u64 t, %1; cvt.u32.u64 %0, t; }" : "=r"(a) : "l"(p));
    return a;
}
__device__ __forceinline__ uint4 ldsm_x4(unsigned addr) {
    uint4 r;
    asm volatile("ldmatrix.sync.aligned.m8n8.x4.shared.b16 {%0,%1,%2,%3}, [%4];"
                 : "=r"(r.x), "=r"(r.y), "=r"(r.z), "=r"(r.w) : "r"(addr));
    return r;
}
__device__ __forceinline__ void mma_bf16(float* c, uint4 a, unsigned b0, unsigned b1) {
    asm volatile(
        "mma.sync.aligned.m16n8k16.row.col.f32.bf16.bf16.f32 "
        "{%0,%1,%2,%3}, {%4,%5,%6,%7}, {%8,%9}, {%0,%1,%2,%3};"
        : "+f"(c[0]), "+f"(c[1]), "+f"(c[2]), "+f"(c[3])
        : "r"(a.x), "r"(a.y), "r"(a.z), "r"(a.w), "r"(b0), "r"(b1));
}
__device__ __forceinline__ unsigned pack_bf16x2(float f0, float f1) {
    unsigned r;
    asm("cvt.rn.bf16x2.f32 %0, %1, %2;" : "=r"(r) : "f"(f1), "f"(f0));
    return r;
}
__device__ __forceinline__ void cp_async16(unsigned sdst, const void* gsrc) {
    unsigned long long g;
    asm("cvta.to.global.u64 %0, %1;" : "=l"(g) : "l"(gsrc));
    asm volatile("cp.async.cg.shared.global [%0], [%1], 16;" :: "r"(sdst), "l"(g) : "memory");
}
#define CP_COMMIT() asm volatile("cp.async.commit_group;" ::: "memory")
#define CP_WAIT0()  asm volatile("cp.async.wait_group 0;" ::: "memory")
#define CP_WAIT1()  asm volatile("cp.async.wait_group 1;" ::: "memory")

// compact index -> (batch, s): largest b with soff[b] <= ci
__device__ __forceinline__ int2 rowmap(const int* soff, int ci) {
    int lo = 0, hi = 32;
    while (lo < hi) {
        int mid = (lo + hi + 1) >> 1;
        if (soff[mid] <= ci) lo = mid; else hi = mid - 1;
    }
    return make_int2(lo, ci - soff[lo]);
}

// rational tanh, 4 at a time, one Newton-refined RCP
__device__ __forceinline__ void tanh4(const float* x, float* y) {
    float al[4], be[4];
#pragma unroll
    for (int i = 0; i < 4; i++) {
        float xc = fminf(fmaxf(x[i], -7.90531110763549805f), 7.90531110763549805f);
        float t = xc * xc;
        float a = -2.76076847742355e-16f;
        a = fmaf(a, t, 2.00018790482477e-13f);
        a = fmaf(a, t, -8.60467152213735e-11f);
        a = fmaf(a, t, 5.12229709037114e-08f);
        a = fmaf(a, t, 1.48572235717979e-05f);
        a = fmaf(a, t, 6.37261928875436e-04f);
        a = fmaf(a, t, 4.89352455891786e-03f);
        al[i] = xc * a;
        float b = 1.19825839466702e-06f;
        b = fmaf(b, t, 1.18534705686654e-04f);
        b = fmaf(b, t, 2.26843463243900e-03f);
        be[i] = fmaf(b, t, 4.89352518554385e-03f);
    }
    float p01 = be[0] * be[1];
    float p23 = be[2] * be[3];
    float p = p01 * p23;
    float r;
    asm("rcp.approx.f32 %0, %1;" : "=f"(r) : "f"(p));
    r = r * fmaf(-p, r, 2.0f);
    float q01 = r * p23, q23 = r * p01;
    y[0] = al[0] * (q01 * be[1]);
    y[1] = al[1] * (q01 * be[0]);
    y[2] = al[2] * (q23 * be[3]);
    y[3] = al[3] * (q23 * be[2]);
}

// ---------------- fused prep kernel (enc split w/ len skip + w2 + t1 + init + prefix) ----------------
#define PREP_ENC_BLKS   16384
#define PREP_W2_BLKS    1024
#define PREP_T1_BLKS    4096
#define PREP_INIT_BLKS  256
#define PREP_GRID (PREP_ENC_BLKS + PREP_W2_BLKS + PREP_T1_BLKS + PREP_INIT_BLKS + 1)

__global__ void k_prep(const float4* __restrict__ enc4,
                       const float* __restrict__ attn_w,
                       const float* __restrict__ attn_b,
                       const float* __restrict__ hidden,
                       const int* __restrict__ lens,
                       float* __restrict__ ctx) {
    int blk = blockIdx.x;
    int tid = threadIdx.x;
    if (blk < PREP_ENC_BLKS) {
        size_t i0 = ((size_t)blk * 256 + tid) * 4;     // float4 index; 256 float4/row
        int row = (int)(i0 >> 8);
        int b = row & (B_DIM - 1), s = row >> 5;
        if (s >= __ldg(&lens[b])) return;
        float4 x[4];
#pragma unroll
        for (int i = 0; i < 4; i++) x[i] = enc4[i0 + i];
        unsigned hi[8], lo[8];
#pragma unroll
        for (int i = 0; i < 4; i++) {
            float hx = __bfloat162float(__float2bfloat16(x[i].x));
            float hy = __bfloat162float(__float2bfloat16(x[i].y));
            float hz = __bfloat162float(__float2bfloat16(x[i].z));
            float hw = __bfloat162float(__float2bfloat16(x[i].w));
            hi[i * 2]     = pack_bf16x2(x[i].x, x[i].y);
            hi[i * 2 + 1] = pack_bf16x2(x[i].z, x[i].w);
            lo[i * 2]     = pack_bf16x2(x[i].x - hx, x[i].y - hy);
            lo[i * 2 + 1] = pack_bf16x2(x[i].z - hz, x[i].w - hw);
        }
        uint4* dh = (uint4*)(g_enc_hi + i0 * 4);
        uint4* dl = (uint4*)(g_enc_lo + i0 * 4);
        dh[0] = make_uint4(hi[0], hi[1], hi[2], hi[3]);
        dh[1] = make_uint4(hi[4], hi[5], hi[6], hi[7]);
        dl[0] = make_uint4(lo[0], lo[1], lo[2], lo[3]);
        dl[1] = make_uint4(lo[4], lo[5], lo[6], lo[7]);
    } else if (blk < PREP_ENC_BLKS + PREP_W2_BLKS) {
        int i = (blk - PREP_ENC_BLKS) * 256 + tid;
        int row = i >> 8, c4 = i & 255;
        float4 x = *(const float4*)(attn_w + (size_t)row * (2 * H_DIM) + H_DIM + c4 * 4);
        float hx = __bfloat162float(__float2bfloat16(x.x));
        float hy = __bfloat162float(__float2bfloat16(x.y));
        float hz = __bfloat162float(__float2bfloat16(x.z));
        float hw = __bfloat162float(__float2bfloat16(x.w));
        ((uint2*)g_w2_hi)[i] = make_uint2(pack_bf16x2(x.x, x.y), pack_bf16x2(x.z, x.w));
        ((uint2*)g_w2_lo)[i] = make_uint2(pack_bf16x2(x.x - hx, x.y - hy),
                                          pack_bf16x2(x.z - hz, x.w - hw));
    } else if (blk < PREP_ENC_BLKS + PREP_W2_BLKS + PREP_T1_BLKS) {
        int w = (blk - PREP_ENC_BLKS - PREP_W2_BLKS) * 8 + (tid >> 5);
        int lane = tid & 31;
        int b = w >> 10;
        int h = w & (H_DIM - 1);
        const float4* hp = (const float4*)(hidden + (size_t)b * H_DIM);
        const float4* wp = (const float4*)(attn_w + (size_t)h * 2 * H_DIM);
        float acc = 0.f;
#pragma unroll
        for (int i = 0; i < 8; i++) {
            int idx = i * 32 + lane;
            float4 hv = hp[idx];
            float4 wv = wp[idx];
            acc += hv.x * wv.x + hv.y * wv.y + hv.z * wv.z + hv.w * wv.w;
        }
#pragma unroll
        for (int off = 16; off; off >>= 1) acc += __shfl_down_sync(0xffffffffu, acc, off);
        if (lane == 0) g_t1[w] = acc + attn_b[h];
    } else if (blk < PREP_ENC_BLKS + PREP_W2_BLKS + PREP_T1_BLKS + PREP_INIT_BLKS) {
        int i = (blk - PREP_ENC_BLKS - PREP_W2_BLKS - PREP_T1_BLKS) * 256 + tid;
        if (i < B_DIM * S_LEN) g_scores[i] = 0.f;
        if (i < B_DIM * H_DIM) ctx[i] = 0.f;
    } else {
        if (tid == 0) {
            int acc = 0;
            g_off[0] = 0;
            for (int b = 0; b < B_DIM; b++) { acc += lens[b]; g_off[b + 1] = acc; }
            g_total = acc;
        }
    }
}

// ---------------- K1: compacted-row GEMM, 128x128 CTA, 2 CTAs/SM ----------------
#define BM 128
#define BN 128
#define BK 32
#define A_HI 0
#define A_LO 8192
#define B_HI 16384
#define B_LO 24576
#define STAGE_B 32768
#define NSTAGE 3
#define VS_OFF  (NSTAGE * STAGE_B)          // 98304: 128 f32
#define SROW_OFF (VS_OFF + 512)             // 98816: 128 f32
#define SOFF_OFF (SROW_OFF + 512)           // 99328: 33 ints
#define K1_SMEM  (SOFF_OFF + 144)           // 99472

__device__ __forceinline__ unsigned sw_off(int row, int c16) {
    return (unsigned)row * 64u + (unsigned)((c16 ^ ((row >> 1) & 3)) << 4);
}

__device__ __forceinline__ void fill_stage(unsigned sb, const size_t* gA, int n0,
                                           int kk, int tid) {
    const int c16 = tid & 3;
    const int lr = tid >> 2;
#pragma unroll
    for (int i = 0; i < 4; i++) {
        size_t goff = gA[i] + kk + c16 * 8;
        unsigned soff = sw_off(i * 32 + lr, c16);
        cp_async16(sb + A_HI + soff, g_enc_hi + goff);
        cp_async16(sb + A_LO + soff, g_enc_lo + goff);
    }
#pragma unroll
    for (int i = 0; i < 4; i++) {
        int idx = i * 128 + tid;
        int row = idx >> 2;
        size_t goff = (size_t)(n0 + row) * H_DIM + kk + c16 * 8;
        unsigned soff = sw_off(row, c16);
        cp_async16(sb + B_HI + soff, g_w2_hi + goff);
        cp_async16(sb + B_LO + soff, g_w2_lo + goff);
    }
}

__global__ void __launch_bounds__(128, 2) k1_gemm(const float* __restrict__ v) {
    const int total = g_total;
    const int m0c = blockIdx.y * BM;
    if (m0c >= total) return;

    extern __shared__ char smem[];
    const unsigned sbase = smem_u32(smem);
    const int tid = threadIdx.x;
    const int wid = tid >> 5;
    const int L = tid & 31;
    const int wm = wid & 1;
    const int wn = wid >> 1;
    const int n0 = blockIdx.x * BN;

    float* vs = (float*)(smem + VS_OFF);
    float* srow = (float*)(smem + SROW_OFF);
    int* soff = (int*)(smem + SOFF_OFF);
    vs[tid] = v[n0 + tid];
    srow[tid] = 0.f;
    if (tid < 33) soff[tid] = g_off[tid];
    __syncthreads();

    size_t gA[4];
#pragma unroll
    for (int i = 0; i < 4; i++) {
        int ci = m0c + i * 32 + (tid >> 2);
        ci = min(ci, total - 1);
        int2 bs = rowmap(soff, ci);
        gA[i] = (size_t)(bs.y * B_DIM + bs.x) * H_DIM;   // r = s*B + b
    }

    fill_stage(sbase, gA, n0, 0, tid);
    CP_COMMIT();
    fill_stage(sbase + STAGE_B, gA, n0, BK, tid);
    CP_COMMIT();

    float acc[4][8][4];
#pragma unroll
    for (int i = 0; i < 4; i++)
#pragma unroll
        for (int j = 0; j < 8; j++)
#pragma unroll
            for (int e = 0; e < 4; e++) acc[i][j][e] = 0.f;

    const int a_r = wm * 64 + ((L >> 3) & 1) * 8 + (L & 7);
    const int a_c = (L >> 4);
    const int b_r = wn * 64 + (L >> 4) * 8 + (L & 7);
    const int b_c = ((L >> 3) & 1);

    const int NKT = H_DIM / BK;              // 32
    int slot = 0, nslot = 2;
    for (int kt = 0; kt < NKT; kt++) {
        if (kt + 1 < NKT) { CP_WAIT1(); } else { CP_WAIT0(); }
        __syncthreads();
        if (kt + 2 < NKT) {
            fill_stage(sbase + nslot * STAGE_B, gA, n0, (kt + 2) * BK, tid);
            CP_COMMIT();
        }
        const unsigned sb = sbase + slot * STAGE_B;
#pragma unroll
        for (int ks = 0; ks < 2; ks++) {
            uint4 ah[4], al[4], bh[4], bl[4];
#pragma unroll
            for (int mf = 0; mf < 4; mf++) {
                int row = a_r + mf * 16;
                unsigned off = sw_off(row, ks * 2 + a_c);
                ah[mf] = ldsm_x4(sb + A_HI + off);
                al[mf] = ldsm_x4(sb + A_LO + off);
            }
#pragma unroll
            for (int nf2 = 0; nf2 < 4; nf2++) {
                int row = b_r + nf2 * 16;
                unsigned off = sw_off(row, ks * 2 + b_c);
                bh[nf2] = ldsm_x4(sb + B_HI + off);
                bl[nf2] = ldsm_x4(sb + B_LO + off);
            }
#pragma unroll
            for (int mf = 0; mf < 4; mf++)
#pragma unroll
                for (int nf2 = 0; nf2 < 4; nf2++) {
                    mma_bf16(acc[mf][nf2 * 2],     ah[mf], bh[nf2].x, bh[nf2].y);
                    mma_bf16(acc[mf][nf2 * 2 + 1], ah[mf], bh[nf2].z, bh[nf2].w);
                }
#pragma unroll
            for (int mf = 0; mf < 4; mf++)
#pragma unroll
                for (int nf2 = 0; nf2 < 4; nf2++) {
                    mma_bf16(acc[mf][nf2 * 2],     ah[mf], bl[nf2].x, bl[nf2].y);
                    mma_bf16(acc[mf][nf2 * 2 + 1], ah[mf], bl[nf2].z, bl[nf2].w);
                }
#pragma unroll
            for (int mf = 0; mf < 4; mf++)
#pragma unroll
                for (int nf2 = 0; nf2 < 4; nf2++) {
                    mma_bf16(acc[mf][nf2 * 2],     al[mf], bh[nf2].x, bh[nf2].y);
                    mma_bf16(acc[mf][nf2 * 2 + 1], al[mf], bh[nf2].z, bh[nf2].w);
                }
        }
        slot = (slot == 2) ? 0 : slot + 1;
        nslot = (nslot == 2) ? 0 : nslot + 1;
    }

    // ---------------- epilogue ----------------
    const int q = L >> 2;
#pragma unroll
    for (int mf = 0; mf < 4; mf++) {
        const int rc0 = m0c + wm * 64 + mf * 16 + q;
        const int rc1 = rc0 + 8;
        int2 bs0 = rowmap(soff, min(rc0, total - 1));
        int2 bs1 = rowmap(soff, min(rc1, total - 1));
        float2 t0a[8], t1a[8];
#pragma unroll
        for (int nf = 0; nf < 8; nf++) {
            const int c = n0 + wn * 64 + nf * 8 + (L & 3) * 2;
            t0a[nf] = __ldg((const float2*)(g_t1 + (size_t)bs0.x * H_DIM + c));
            t1a[nf] = __ldg((const float2*)(g_t1 + (size_t)bs1.x * H_DIM + c));
        }
        float rp0 = 0.f, rp1 = 0.f;
#pragma unroll
        for (int nf = 0; nf < 8; nf++) {
            const int cl = wn * 64 + nf * 8 + (L & 3) * 2;
            float x[4], y[4];
            x[0] = acc[mf][nf][0] + t0a[nf].x;
            x[1] = acc[mf][nf][1] + t0a[nf].y;
            x[2] = acc[mf][nf][2] + t1a[nf].x;
            x[3] = acc[mf][nf][3] + t1a[nf].y;
            tanh4(x, y);
            rp0 += y[0] * vs[cl] + y[1] * vs[cl + 1];
            rp1 += y[2] * vs[cl] + y[3] * vs[cl + 1];
        }
        rp0 += __shfl_xor_sync(0xffffffffu, rp0, 1);
        rp0 += __shfl_xor_sync(0xffffffffu, rp0, 2);
        rp1 += __shfl_xor_sync(0xffffffffu, rp1, 1);
        rp1 += __shfl_xor_sync(0xffffffffu, rp1, 2);
        if ((L & 3) == 0) {
            atomicAdd(&srow[wm * 64 + mf * 16 + q], rp0);
            atomicAdd(&srow[wm * 64 + mf * 16 + q + 8], rp1);
        }
    }
    __syncthreads();
    {
        int rc = m0c + tid;
        if (rc < total) {
            int2 bs = rowmap(soff, rc);
            atomicAdd(&g_scores[bs.x * S_LEN + bs.y], srow[tid]);
        }
    }
}

// ---------------- softmax: exp folded into pass 2, pass 3 rescales from L2 ----------------
__global__ void k2_softmax(const int* __restrict__ lens, float* __restrict__ wout) {
    __shared__ float red[256];
    int b = blockIdx.x;
    int len = lens[b];
    const float* sc = g_scores + (size_t)b * S_LEN;
    float* wrow = wout + (size_t)b * S_LEN;
    int tid = threadIdx.x;

    float mx = -3.4e38f;
    for (int s = tid; s < len; s += 256) mx = fmaxf(mx, sc[s]);
    red[tid] = mx;
    __syncthreads();
    for (int off = 128; off; off >>= 1) {
        if (tid < off) red[tid] = fmaxf(red[tid], red[tid + off]);
        __syncthreads();
    }
    mx = red[0];
    __syncthreads();

    float sum = 0.f;
    for (int s = tid; s < S_LEN; s += 256) {
        float e = (s < len) ? expf(sc[s] - mx) : 0.f;
        wrow[s] = e;
        sum += e;
    }
    red[tid] = sum;
    __syncthreads();
    for (int off = 128; off; off >>= 1) {
        if (tid < off) red[tid] += red[tid + off];
        __syncthreads();
    }
    float inv = 1.f / red[0];

    for (int s = tid; s < len; s += 256)
        wrow[s] *= inv;
}

// ---------------- context (R13-exact) ----------------
#define NCHUNK 64
__global__ void k3_context(const float* __restrict__ enc,
                           const float* __restrict__ wts,
                           const int* __restrict__ lens,
                           float* __restrict__ ctx) {
    int b = blockIdx.y;
    int len = lens[b];
    int s0 = blockIdx.x * (S_LEN / NCHUNK);
    int s1 = min(s0 + (S_LEN / NCHUNK), len);
    if (s0 >= s1) return;
    int h = threadIdx.x * 4;
    float4 acc = make_float4(0.f, 0.f, 0.f, 0.f);
    for (int s = s0; s < s1; s++) {
        float w = __ldg(&wts[(size_t)b * S_LEN + s]);
        float4 e = *(const float4*)(enc + ((size_t)(s * B_DIM + b)) * H_DIM + h);
        acc.x += w * e.x; acc.y += w * e.y; acc.z += w * e.z; acc.w += w * e.w;
    }
    float* c = ctx + (size_t)b * H_DIM + h;
    atomicAdd(c + 0, acc.x);
    atomicAdd(c + 1, acc.y);
    atomicAdd(c + 2, acc.z);
    atomicAdd(c + 3, acc.w);
}

// ---------------- launcher ----------------
extern "C" void kernel_launch(void* const* d_in, const int* in_sizes, int n_in,
                              void* d_out, int out_size) {
    const float* hidden = (const float*)d_in[0];
    const float* enc    = (const float*)d_in[1];
    const int*   lens   = (const int*)d_in[2];
    const float* attn_w = (const float*)d_in[3];
    const float* attn_b = (const float*)d_in[4];
    const float* v      = (const float*)d_in[5];

    float* out = (float*)d_out;
    float* ctx = out;
    float* wts = out + B_DIM * H_DIM;

    cudaFuncSetAttribute(k1_gemm, cudaFuncAttributeMaxDynamicSharedMemorySize, K1_SMEM);

    k_prep<<<PREP_GRID, 256>>>((const float4*)enc, attn_w, attn_b, hidden, lens, ctx);
    dim3 g1(H_DIM / BN, M_TOT / BM);     // (8, 512); CTAs beyond g_total exit early
    k1_gemm<<<g1, 128, K1_SMEM>>>(v);
    k2_softmax<<<B_DIM, 256>>>(lens, wts);
    dim3 g3(NCHUNK, B_DIM);
    k3_context<<<g3, 256>>>(enc, wts, lens, ctx);
}